// round 16
// baseline (speedup 1.0000x reference)
#include <cuda_runtime.h>
#include <cuda_fp16.h>
#include <cstdint>

// RBFN fused kernel: R15 compute + triple-buffered C/W/c2, ONE barrier per unit.
// out[8192,64] = sqrt(1 + max(x2 + c2 - 2*X@C^T, 0)) @ W

#define D_TOT   8192
#define N_TOT   8192
#define KD      128
#define LD      64
#define BD      128
#define BN      128
#define TILES   (D_TOT / BD)            // 64
#define CPT     (N_TOT / BN)            // 64
#define UNITS   (TILES * CPT)           // 4096
#define THREADS 256

// shared memory layout (32-bit word offsets)
#define XH_O 0                    // X tile  [2][128][68] half2 words
#define CH_O 17408                // C chunk [3][128][68]
#define WS_O 43520                // W^T     [3][64][68]
#define X2_O 56576                // [2][128]
#define C2_O 56832                // [3][128]
#define SM_WORDS 57216
#define SMEM_BYTES (SM_WORDS * 4)   // 228,864 B

#define XH_BUF 8704
#define CH_BUF 8704
#define WS_BUF 4352

__device__ float  x2_g[D_TOT];
__device__ float  c2_g[N_TOT];
__device__ __half xh_g[D_TOT * KD];
__device__ __half ch_g[N_TOT * KD];
__device__ __half wt_g[LD * N_TOT];    // fp16 weight, TRANSPOSED [l][n]

// ------------------------- helpers -------------------------
__device__ __forceinline__ uint32_t smem_u32(const void* p) {
    uint32_t a;
    asm("{ .reg .u64 t; cvta.to.shared.u64 t, %1; cvt.u32.u64 %0, t; }" : "=r"(a) : "l"(p));
    return a;
}
__device__ __forceinline__ float fsqrt_ap(float x) {
    float r; asm("sqrt.approx.f32 %0, %1;" : "=f"(r) : "f"(x)); return r;
}
__device__ __forceinline__ void cp16(uint32_t dst, const void* src) {
    asm volatile("cp.async.ca.shared.global [%0], [%1], 16;" :: "r"(dst), "l"(src) : "memory");
}
__device__ __forceinline__ void cpcommit() {
    asm volatile("cp.async.commit_group;" ::: "memory");
}
template <int N>
__device__ __forceinline__ void cpwait() {
    asm volatile("cp.async.wait_group %0;" :: "n"(N) : "memory");
}
__device__ __forceinline__ void ldsm4(uint32_t* r, uint32_t addr) {
    asm volatile("ldmatrix.sync.aligned.m8n8.x4.shared.b16 {%0,%1,%2,%3}, [%4];"
                 : "=r"(r[0]), "=r"(r[1]), "=r"(r[2]), "=r"(r[3]) : "r"(addr));
}
__device__ __forceinline__ void mma_f16(float* d, const uint32_t* a, const uint32_t* b) {
    asm volatile("mma.sync.aligned.m16n8k16.row.col.f32.f16.f16.f32 "
                 "{%0,%1,%2,%3}, {%4,%5,%6,%7}, {%8,%9}, {%0,%1,%2,%3};"
                 : "+f"(d[0]), "+f"(d[1]), "+f"(d[2]), "+f"(d[3])
                 : "r"(a[0]), "r"(a[1]), "r"(a[2]), "r"(a[3]),
                   "r"(b[0]), "r"(b[1]));
}

// ---------------------------------------------------------------------------
// Prologue. Blocks [0,128): W transpose (first). [128,640): norms (MLP 4)+zero.
// ---------------------------------------------------------------------------
__global__ void prologue_kernel(const float* __restrict__ xs,
                                const float* __restrict__ centre,
                                const float* __restrict__ weight,
                                float* __restrict__ out) {
    __shared__ float ts[64 * 65];
    const int tid = threadIdx.x;
    if (blockIdx.x < 128) {
        int nb = blockIdx.x * 64;
        #pragma unroll
        for (int it = 0; it < 16; ++it) {
            int idx = it * THREADS + tid;
            int n_loc = idx >> 6, l = idx & 63;
            ts[n_loc * 65 + l] = weight[(size_t)(nb + n_loc) * LD + l];
        }
        __syncthreads();
        #pragma unroll
        for (int it = 0; it < 16; ++it) {
            int idx = it * THREADS + tid;
            int l = idx >> 6, n_loc = idx & 63;
            wt_g[(size_t)l * N_TOT + nb + n_loc] = __float2half_rn(ts[n_loc * 65 + l]);
        }
    } else {
        const int nb = blockIdx.x - 128;
        ((float4*)out)[nb * THREADS + tid] = make_float4(0.f, 0.f, 0.f, 0.f);

        const int wid  = tid >> 5, lane = tid & 31;
        const int r0   = nb * 32 + wid * 4;
        const float* src; float* dst; __half* dsth; int row;
        if (r0 < D_TOT) { src = xs;     dst = x2_g; dsth = xh_g; row = r0; }
        else            { src = centre; dst = c2_g; dsth = ch_g; row = r0 - D_TOT; }

        float4 v[4];
        #pragma unroll
        for (int i = 0; i < 4; ++i)
            v[i] = ((const float4*)(src + (size_t)(row + i) * KD))[lane];

        float s[4];
        #pragma unroll
        for (int i = 0; i < 4; ++i) {
            __half2 h01 = __float22half2_rn(make_float2(v[i].x, v[i].y));
            __half2 h23 = __float22half2_rn(make_float2(v[i].z, v[i].w));
            *(uint2*)(dsth + (size_t)(row + i) * KD + 4 * lane) =
                make_uint2(*(uint32_t*)&h01, *(uint32_t*)&h23);
            s[i] = v[i].x * v[i].x + v[i].y * v[i].y + v[i].z * v[i].z + v[i].w * v[i].w;
        }
        #pragma unroll
        for (int off = 16; off; off >>= 1) {
            #pragma unroll
            for (int i = 0; i < 4; ++i)
                s[i] += __shfl_xor_sync(0xffffffffu, s[i], off);
        }
        if (lane < 4) dst[row + lane] = s[lane];
    }
}

// ---------------------------------------------------------------------------
// Issue loads for unit u into 3-deep buffer slot b3 (C/W/c2), X if withX.
// ---------------------------------------------------------------------------
__device__ __forceinline__ void issue_unit(uint32_t sb, int tid, int u, int b3,
                                           bool withX) {
    const int chunk = u & (CPT - 1);
    const int nb    = chunk * BN;
    const int tile  = u >> 6;

    if (withX) {
        const int xpar = tile & 1;
        const int db   = tile * BD;
        #pragma unroll 1
        for (int it = 0; it < 8; ++it) {
            int idx = it * THREADS + tid;
            int row = idx >> 4, qc = idx & 15;
            cp16(sb + (XH_O + xpar * XH_BUF + row * 68 + qc * 4) * 4,
                 xh_g + (size_t)(db + row) * KD + qc * 8);
        }
        if (tid < 32) cp16(sb + (X2_O + xpar * 128 + tid * 4) * 4, x2_g + db + tid * 4);
    }
    #pragma unroll 1
    for (int it = 0; it < 8; ++it) {
        int idx = it * THREADS + tid;
        int row = idx >> 4, qc = idx & 15;
        cp16(sb + (CH_O + b3 * CH_BUF + row * 68 + qc * 4) * 4,
             ch_g + (size_t)(nb + row) * KD + qc * 8);
    }
    #pragma unroll 1
    for (int it = 0; it < 4; ++it) {
        int idx = it * THREADS + tid;
        int l = idx >> 4, qc = idx & 15;
        cp16(sb + (WS_O + b3 * WS_BUF + l * 68 + qc * 4) * 4,
             wt_g + (size_t)l * N_TOT + nb + qc * 8);
    }
    if (tid < 32) cp16(sb + (C2_O + b3 * 128 + tid * 4) * 4, c2_g + nb + tid * 4);
    cpcommit();
}

// ---------------------------------------------------------------------------
// Main persistent kernel. One __syncthreads per unit (triple-buffered).
// Warp (wm, h): wm = wid & 3 -> 32-row band; h = wid >> 2 -> 64-col k-half.
// ---------------------------------------------------------------------------
__global__ __launch_bounds__(THREADS, 1)
void rbfn_main_kernel(float* __restrict__ out) {
    extern __shared__ float smf[];
    const uint32_t sb = smem_u32(smf);

    const int tid = threadIdx.x;
    const int wid = tid >> 5, lid = tid & 31;
    const int gid = lid >> 2, ctg = lid & 3;
    const int RM  = (wid & 3) * 32;
    const int h   = wid >> 2;
    const int CN1 = h * 64;

    const int lm8  = (lid >> 3) & 1;
    const int lm16 = lid >> 4;
    const int lr   = lid & 7;
    const int aRow0 = RM + lm8 * 8 + lr;
    const int aRow1 = aRow0 + 16;
    const int aColB = lm16 * 4;
    const int bColB = lm8 * 4;
    int bRow[4], wRow[4];
    #pragma unroll
    for (int ntp = 0; ntp < 4; ++ntp) {
        bRow[ntp] = CN1 + ntp * 16 + lm16 * 8 + lr;
        wRow[ntp] = ntp * 16 + lm16 * 8 + lr;
    }

    const int u0 = (int)(((long long)blockIdx.x * UNITS) / gridDim.x);
    const int u1 = (int)(((long long)(blockIdx.x + 1) * UNITS) / gridDim.x);

    int pcur = u0 % 3;
    issue_unit(sb, tid, u0, pcur, true);

    float O[2][8][4];
    #pragma unroll
    for (int mt = 0; mt < 2; ++mt)
        #pragma unroll
        for (int nt = 0; nt < 8; ++nt)
            #pragma unroll
            for (int r = 0; r < 4; ++r) O[mt][nt][r] = 0.f;

    #pragma unroll 1
    for (int u = u0; u < u1; ++u) {
        const int tile = u >> 6;
        const int xpar = tile & 1;
        const int pnxt = (pcur == 2) ? 0 : pcur + 1;

        if (u + 1 < u1) {
            issue_unit(sb, tid, u + 1, pnxt, ((u + 1) >> 6) != tile);
            cpwait<1>();
        } else {
            cpwait<0>();
        }
        __syncthreads();                 // unit u data visible to ALL threads

        const uint32_t xh_b = sb + (XH_O + xpar * XH_BUF) * 4;
        const uint32_t ch_b = sb + (CH_O + pcur * CH_BUF) * 4;
        const uint32_t ws_b = sb + (WS_O + pcur * WS_BUF) * 4;

        // ---- hoist per-lane (1 + c2) for this warp's 8 columns ----
        float cpre[4][2], cpre1[4][2];
        #pragma unroll
        for (int ks = 0; ks < 4; ++ks) {
            #pragma unroll
            for (int t = 0; t < 2; ++t) {
                int c0 = CN1 + (2 * ks + t) * 8 + 2 * ctg;
                cpre[ks][t]  = 1.f + smf[C2_O + pcur * 128 + c0];
                cpre1[ks][t] = 1.f + smf[C2_O + pcur * 128 + c0 + 1];
            }
        }

        // ---- GEMM1: software-pipelined over kw ----
        float S[2][8][4];
        #pragma unroll
        for (int mt = 0; mt < 2; ++mt)
            #pragma unroll
            for (int nt = 0; nt < 8; ++nt)
                #pragma unroll
                for (int r = 0; r < 4; ++r) S[mt][nt][r] = 0.f;

        uint32_t a[2][2][4], bb[2][4][4];
        ldsm4(a[0][0], xh_b + (uint32_t)(aRow0 * 68 + 0 + aColB) * 4);
        ldsm4(a[0][1], xh_b + (uint32_t)(aRow1 * 68 + 0 + aColB) * 4);
        #pragma unroll
        for (int ntp = 0; ntp < 4; ++ntp)
            ldsm4(bb[0][ntp], ch_b + (uint32_t)(bRow[ntp] * 68 + 0 + bColB) * 4);

        #pragma unroll
        for (int ki = 0; ki < 8; ++ki) {
            const int cur = ki & 1, nxt = cur ^ 1;
            if (ki < 7) {
                const int kw = (ki + 1) * 8;
                ldsm4(a[nxt][0], xh_b + (uint32_t)(aRow0 * 68 + kw + aColB) * 4);
                ldsm4(a[nxt][1], xh_b + (uint32_t)(aRow1 * 68 + kw + aColB) * 4);
                #pragma unroll
                for (int ntp = 0; ntp < 4; ++ntp)
                    ldsm4(bb[nxt][ntp], ch_b + (uint32_t)(bRow[ntp] * 68 + kw + bColB) * 4);
            }
            #pragma unroll
            for (int mt = 0; mt < 2; ++mt)
                #pragma unroll
                for (int nt = 0; nt < 8; ++nt)
                    mma_f16(S[mt][nt], a[cur][mt], &bb[cur][nt >> 1][(nt & 1) * 2]);
        }

        // ---- epilogue + GEMM2, W frags prefetched one ks ahead ----
        const float xA0 = smf[X2_O + xpar * 128 + RM + gid];
        const float xB0 = smf[X2_O + xpar * 128 + RM + gid + 8];
        const float xA1 = smf[X2_O + xpar * 128 + RM + 16 + gid];
        const float xB1 = smf[X2_O + xpar * 128 + RM + 16 + gid + 8];

        uint32_t wb[2][4][4];
        #pragma unroll
        for (int ntp = 0; ntp < 4; ++ntp)
            ldsm4(wb[0][ntp], ws_b + (uint32_t)(wRow[ntp] * 68 + h * 32 + 0 + bColB) * 4);

        #pragma unroll
        for (int ks = 0; ks < 4; ++ks) {
            const int cur = ks & 1, nxt = cur ^ 1;
            if (ks < 3) {
                #pragma unroll
                for (int ntp = 0; ntp < 4; ++ntp)
                    ldsm4(wb[nxt][ntp],
                          ws_b + (uint32_t)(wRow[ntp] * 68 + h * 32 + (ks + 1) * 8 + bColB) * 4);
            }
            uint32_t afrag[2][4];
            #pragma unroll
            for (int mt = 0; mt < 2; ++mt) {
                const float xA = mt ? xA1 : xA0;
                const float xB = mt ? xB1 : xB0;
                #pragma unroll
                for (int t = 0; t < 2; ++t) {
                    const int nt = 2 * ks + t;
                    const float u0c = xA + cpre[ks][t];
                    const float u1c = xA + cpre1[ks][t];
                    const float v0c = xB + cpre[ks][t];
                    const float v1c = xB + cpre1[ks][t];
                    float p0 = fsqrt_ap(fmaxf(fmaf(-2.f, S[mt][nt][0], u0c), 1.f));
                    float p1 = fsqrt_ap(fmaxf(fmaf(-2.f, S[mt][nt][1], u1c), 1.f));
                    float p2 = fsqrt_ap(fmaxf(fmaf(-2.f, S[mt][nt][2], v0c), 1.f));
                    float p3 = fsqrt_ap(fmaxf(fmaf(-2.f, S[mt][nt][3], v1c), 1.f));
                    __half2 hA = __floats2half2_rn(p0, p1);
                    __half2 hB = __floats2half2_rn(p2, p3);
                    afrag[mt][2 * t]     = *(uint32_t*)&hA;
                    afrag[mt][2 * t + 1] = *(uint32_t*)&hB;
                }
            }
            #pragma unroll
            for (int nt = 0; nt < 8; ++nt) {
                mma_f16(O[0][nt], afrag[0], &wb[cur][nt >> 1][(nt & 1) * 2]);
                mma_f16(O[1][nt], afrag[1], &wb[cur][nt >> 1][(nt & 1) * 2]);
            }
        }

        // ---- flush O at tile boundary / end ----
        if (u + 1 == u1 || ((u + 1) >> 6) != tile) {
            #pragma unroll
            for (int mt = 0; mt < 2; ++mt) {
                int rA = tile * BD + RM + mt * 16 + gid;
                #pragma unroll
                for (int nt = 0; nt < 8; ++nt) {
                    int c0 = nt * 8 + 2 * ctg;
                    atomicAdd(&out[(size_t)rA * LD + c0],           O[mt][nt][0]);
                    atomicAdd(&out[(size_t)rA * LD + c0 + 1],       O[mt][nt][1]);
                    atomicAdd(&out[(size_t)(rA + 8) * LD + c0],     O[mt][nt][2]);
                    atomicAdd(&out[(size_t)(rA + 8) * LD + c0 + 1], O[mt][nt][3]);
                    O[mt][nt][0] = O[mt][nt][1] = O[mt][nt][2] = O[mt][nt][3] = 0.f;
                }
            }
        }
        pcur = pnxt;
    }
}

// ---------------------------------------------------------------------------
extern "C" void kernel_launch(void* const* d_in, const int* in_sizes, int n_in,
                              void* d_out, int out_size) {
    const float* xs     = (const float*)d_in[0];
    const float* centre = (const float*)d_in[1];
    const float* weight = (const float*)d_in[2];
    float* out = (float*)d_out;

    int nsm = 0;
    cudaDeviceGetAttribute(&nsm, cudaDevAttrMultiProcessorCount, 0);
    if (nsm <= 0) nsm = 128;
    if (nsm > UNITS) nsm = UNITS;

    cudaFuncSetAttribute(rbfn_main_kernel,
                         cudaFuncAttributeMaxDynamicSharedMemorySize, SMEM_BYTES);

    prologue_kernel<<<128 + 512, THREADS>>>(xs, centre, weight, out);
    rbfn_main_kernel<<<nsm, THREADS, SMEM_BYTES>>>(out);
}

// round 17
// speedup vs baseline: 1.0428x; 1.0428x over previous
#include <cuda_runtime.h>
#include <cuda_fp16.h>
#include <cstdint>

// RBFN fused kernel (R15 = best) + programmatic dependent launch to overlap
// the prologue tail with main-kernel launch.
// out[8192,64] = sqrt(1 + max(x2 + c2 - 2*X@C^T, 0)) @ W

#define D_TOT   8192
#define N_TOT   8192
#define KD      128
#define LD      64
#define BD      128
#define BN      128
#define TILES   (D_TOT / BD)            // 64
#define CPT     (N_TOT / BN)            // 64
#define UNITS   (TILES * CPT)           // 4096
#define THREADS 256

// shared memory layout (32-bit word offsets)
#define XH_O 0                    // X tile  [2][128][68] half2 words
#define CH_O 17408                // C chunk [2][128][68]
#define WS_O 34816                // W^T     [2][64][68]
#define X2_O 43520                // [2][128]
#define C2_O 43776                // [2][128]
#define SM_WORDS 44032
#define SMEM_BYTES (SM_WORDS * 4)

#define XH_BUF 8704
#define CH_BUF 8704
#define WS_BUF 4352

__device__ float  x2_g[D_TOT];
__device__ float  c2_g[N_TOT];
__device__ __half xh_g[D_TOT * KD];
__device__ __half ch_g[N_TOT * KD];
__device__ __half wt_g[LD * N_TOT];    // fp16 weight, TRANSPOSED [l][n]

// ------------------------- helpers -------------------------
__device__ __forceinline__ uint32_t smem_u32(const void* p) {
    uint32_t a;
    asm("{ .reg .u64 t; cvta.to.shared.u64 t, %1; cvt.u32.u64 %0, t; }" : "=r"(a) : "l"(p));
    return a;
}
__device__ __forceinline__ float fsqrt_ap(float x) {
    float r; asm("sqrt.approx.f32 %0, %1;" : "=f"(r) : "f"(x)); return r;
}
__device__ __forceinline__ void cp16(uint32_t dst, const void* src) {
    asm volatile("cp.async.ca.shared.global [%0], [%1], 16;" :: "r"(dst), "l"(src) : "memory");
}
__device__ __forceinline__ void cpcommit() {
    asm volatile("cp.async.commit_group;" ::: "memory");
}
template <int N>
__device__ __forceinline__ void cpwait() {
    asm volatile("cp.async.wait_group %0;" :: "n"(N) : "memory");
}
__device__ __forceinline__ void ldsm4(uint32_t* r, uint32_t addr) {
    asm volatile("ldmatrix.sync.aligned.m8n8.x4.shared.b16 {%0,%1,%2,%3}, [%4];"
                 : "=r"(r[0]), "=r"(r[1]), "=r"(r[2]), "=r"(r[3]) : "r"(addr));
}
__device__ __forceinline__ void mma_f16(float* d, const uint32_t* a, const uint32_t* b) {
    asm volatile("mma.sync.aligned.m16n8k16.row.col.f32.f16.f16.f32 "
                 "{%0,%1,%2,%3}, {%4,%5,%6,%7}, {%8,%9}, {%0,%1,%2,%3};"
                 : "+f"(d[0]), "+f"(d[1]), "+f"(d[2]), "+f"(d[3])
                 : "r"(a[0]), "r"(a[1]), "r"(a[2]), "r"(a[3]),
                   "r"(b[0]), "r"(b[1]));
}

// ---------------------------------------------------------------------------
// Prologue. Blocks [0,128): W transpose (first). [128,640): norms (MLP 4)+zero.
// Ends with griddepcontrol.launch_dependents (PDL trigger).
// ---------------------------------------------------------------------------
__global__ void prologue_kernel(const float* __restrict__ xs,
                                const float* __restrict__ centre,
                                const float* __restrict__ weight,
                                float* __restrict__ out) {
    __shared__ float ts[64 * 65];
    const int tid = threadIdx.x;
    if (blockIdx.x < 128) {
        int nb = blockIdx.x * 64;
        #pragma unroll
        for (int it = 0; it < 16; ++it) {
            int idx = it * THREADS + tid;
            int n_loc = idx >> 6, l = idx & 63;
            ts[n_loc * 65 + l] = weight[(size_t)(nb + n_loc) * LD + l];
        }
        __syncthreads();
        #pragma unroll
        for (int it = 0; it < 16; ++it) {
            int idx = it * THREADS + tid;
            int l = idx >> 6, n_loc = idx & 63;
            wt_g[(size_t)l * N_TOT + nb + n_loc] = __float2half_rn(ts[n_loc * 65 + l]);
        }
    } else {
        const int nb = blockIdx.x - 128;
        ((float4*)out)[nb * THREADS + tid] = make_float4(0.f, 0.f, 0.f, 0.f);

        const int wid  = tid >> 5, lane = tid & 31;
        const int r0   = nb * 32 + wid * 4;
        const float* src; float* dst; __half* dsth; int row;
        if (r0 < D_TOT) { src = xs;     dst = x2_g; dsth = xh_g; row = r0; }
        else            { src = centre; dst = c2_g; dsth = ch_g; row = r0 - D_TOT; }

        float4 v[4];
        #pragma unroll
        for (int i = 0; i < 4; ++i)
            v[i] = ((const float4*)(src + (size_t)(row + i) * KD))[lane];

        float s[4];
        #pragma unroll
        for (int i = 0; i < 4; ++i) {
            __half2 h01 = __float22half2_rn(make_float2(v[i].x, v[i].y));
            __half2 h23 = __float22half2_rn(make_float2(v[i].z, v[i].w));
            *(uint2*)(dsth + (size_t)(row + i) * KD + 4 * lane) =
                make_uint2(*(uint32_t*)&h01, *(uint32_t*)&h23);
            s[i] = v[i].x * v[i].x + v[i].y * v[i].y + v[i].z * v[i].z + v[i].w * v[i].w;
        }
        #pragma unroll
        for (int off = 16; off; off >>= 1) {
            #pragma unroll
            for (int i = 0; i < 4; ++i)
                s[i] += __shfl_xor_sync(0xffffffffu, s[i], off);
        }
        if (lane < 4) dst[row + lane] = s[lane];
    }
    asm volatile("griddepcontrol.launch_dependents;" ::: "memory");
}

// ---------------------------------------------------------------------------
// Issue loads for unit u (C/W/c2, plus X/x2 if withX). One commit group.
// ---------------------------------------------------------------------------
__device__ __forceinline__ void issue_unit(uint32_t sb, int tid, int u, bool withX) {
    const int par   = u & 1;
    const int chunk = u & (CPT - 1);
    const int nb    = chunk * BN;
    const int tile  = u >> 6;

    if (withX) {
        const int xpar = tile & 1;
        const int db   = tile * BD;
        #pragma unroll 1
        for (int it = 0; it < 8; ++it) {
            int idx = it * THREADS + tid;
            int row = idx >> 4, qc = idx & 15;
            cp16(sb + (XH_O + xpar * XH_BUF + row * 68 + qc * 4) * 4,
                 xh_g + (size_t)(db + row) * KD + qc * 8);
        }
        if (tid < 32) cp16(sb + (X2_O + xpar * 128 + tid * 4) * 4, x2_g + db + tid * 4);
    }
    #pragma unroll 1
    for (int it = 0; it < 8; ++it) {
        int idx = it * THREADS + tid;
        int row = idx >> 4, qc = idx & 15;
        cp16(sb + (CH_O + par * CH_BUF + row * 68 + qc * 4) * 4,
             ch_g + (size_t)(nb + row) * KD + qc * 8);
    }
    #pragma unroll 1
    for (int it = 0; it < 4; ++it) {
        int idx = it * THREADS + tid;
        int l = idx >> 4, qc = idx & 15;
        cp16(sb + (WS_O + par * WS_BUF + l * 68 + qc * 4) * 4,
             wt_g + (size_t)l * N_TOT + nb + qc * 8);
    }
    if (tid < 32) cp16(sb + (C2_O + par * 128 + tid * 4) * 4, c2_g + nb + tid * 4);
    cpcommit();
}

// ---------------------------------------------------------------------------
// Main persistent kernel (R15). Opens with griddepcontrol.wait (PDL).
// Warp (wm, h): wm = wid & 3 -> 32-row band; h = wid >> 2 -> 64-col k-half.
// ---------------------------------------------------------------------------
__global__ __launch_bounds__(THREADS, 1)
void rbfn_main_kernel(float* __restrict__ out) {
    extern __shared__ float smf[];
    const uint32_t sb = smem_u32(smf);

    const int tid = threadIdx.x;
    const int wid = tid >> 5, lid = tid & 31;
    const int gid = lid >> 2, ctg = lid & 3;
    const int RM  = (wid & 3) * 32;
    const int h   = wid >> 2;
    const int CN1 = h * 64;

    const int lm8  = (lid >> 3) & 1;
    const int lm16 = lid >> 4;
    const int lr   = lid & 7;
    const int aRow0 = RM + lm8 * 8 + lr;
    const int aRow1 = aRow0 + 16;
    const int aColB = lm16 * 4;
    const int bColB = lm8 * 4;
    int bRow[4], wRow[4];
    #pragma unroll
    for (int ntp = 0; ntp < 4; ++ntp) {
        bRow[ntp] = CN1 + ntp * 16 + lm16 * 8 + lr;
        wRow[ntp] = ntp * 16 + lm16 * 8 + lr;
    }

    const int u0 = (int)(((long long)blockIdx.x * UNITS) / gridDim.x);
    const int u1 = (int)(((long long)(blockIdx.x + 1) * UNITS) / gridDim.x);

    asm volatile("griddepcontrol.wait;" ::: "memory");   // prologue writes visible

    issue_unit(sb, tid, u0, true);

    float O[2][8][4];
    #pragma unroll
    for (int mt = 0; mt < 2; ++mt)
        #pragma unroll
        for (int nt = 0; nt < 8; ++nt)
            #pragma unroll
            for (int r = 0; r < 4; ++r) O[mt][nt][r] = 0.f;

    #pragma unroll 1
    for (int u = u0; u < u1; ++u) {
        const int tile = u >> 6;
        const int par  = u & 1;
        const int xpar = tile & 1;

        __syncthreads();
        if (u + 1 < u1)
            issue_unit(sb, tid, u + 1, ((u + 1) >> 6) != tile);
        if (u + 1 < u1) cpwait<1>(); else cpwait<0>();
        __syncthreads();

        const uint32_t xh_b = sb + (XH_O + xpar * XH_BUF) * 4;
        const uint32_t ch_b = sb + (CH_O + par * CH_BUF) * 4;
        const uint32_t ws_b = sb + (WS_O + par * WS_BUF) * 4;

        // ---- hoist per-lane (1 + c2) for this warp's 8 columns ----
        float cpre[4][2], cpre1[4][2];
        #pragma unroll
        for (int ks = 0; ks < 4; ++ks) {
            #pragma unroll
            for (int t = 0; t < 2; ++t) {
                int c0 = CN1 + (2 * ks + t) * 8 + 2 * ctg;
                cpre[ks][t]  = 1.f + smf[C2_O + par * 128 + c0];
                cpre1[ks][t] = 1.f + smf[C2_O + par * 128 + c0 + 1];
            }
        }

        // ---- GEMM1: software-pipelined over kw ----
        float S[2][8][4];
        #pragma unroll
        for (int mt = 0; mt < 2; ++mt)
            #pragma unroll
            for (int nt = 0; nt < 8; ++nt)
                #pragma unroll
                for (int r = 0; r < 4; ++r) S[mt][nt][r] = 0.f;

        uint32_t a[2][2][4], bb[2][4][4];
        ldsm4(a[0][0], xh_b + (uint32_t)(aRow0 * 68 + 0 + aColB) * 4);
        ldsm4(a[0][1], xh_b + (uint32_t)(aRow1 * 68 + 0 + aColB) * 4);
        #pragma unroll
        for (int ntp = 0; ntp < 4; ++ntp)
            ldsm4(bb[0][ntp], ch_b + (uint32_t)(bRow[ntp] * 68 + 0 + bColB) * 4);

        #pragma unroll
        for (int ki = 0; ki < 8; ++ki) {
            const int cur = ki & 1, nxt = cur ^ 1;
            if (ki < 7) {
                const int kw = (ki + 1) * 8;
                ldsm4(a[nxt][0], xh_b + (uint32_t)(aRow0 * 68 + kw + aColB) * 4);
                ldsm4(a[nxt][1], xh_b + (uint32_t)(aRow1 * 68 + kw + aColB) * 4);
                #pragma unroll
                for (int ntp = 0; ntp < 4; ++ntp)
                    ldsm4(bb[nxt][ntp], ch_b + (uint32_t)(bRow[ntp] * 68 + kw + bColB) * 4);
            }
            #pragma unroll
            for (int mt = 0; mt < 2; ++mt)
                #pragma unroll
                for (int nt = 0; nt < 8; ++nt)
                    mma_f16(S[mt][nt], a[cur][mt], &bb[cur][nt >> 1][(nt & 1) * 2]);
        }

        // ---- epilogue + GEMM2, W frags prefetched one ks ahead ----
        const float xA0 = smf[X2_O + xpar * 128 + RM + gid];
        const float xB0 = smf[X2_O + xpar * 128 + RM + gid + 8];
        const float xA1 = smf[X2_O + xpar * 128 + RM + 16 + gid];
        const float xB1 = smf[X2_O + xpar * 128 + RM + 16 + gid + 8];

        uint32_t wb[2][4][4];
        #pragma unroll
        for (int ntp = 0; ntp < 4; ++ntp)
            ldsm4(wb[0][ntp], ws_b + (uint32_t)(wRow[ntp] * 68 + h * 32 + 0 + bColB) * 4);

        #pragma unroll
        for (int ks = 0; ks < 4; ++ks) {
            const int cur = ks & 1, nxt = cur ^ 1;
            if (ks < 3) {
                #pragma unroll
                for (int ntp = 0; ntp < 4; ++ntp)
                    ldsm4(wb[nxt][ntp],
                          ws_b + (uint32_t)(wRow[ntp] * 68 + h * 32 + (ks + 1) * 8 + bColB) * 4);
            }
            uint32_t afrag[2][4];
            #pragma unroll
            for (int mt = 0; mt < 2; ++mt) {
                const float xA = mt ? xA1 : xA0;
                const float xB = mt ? xB1 : xB0;
                #pragma unroll
                for (int t = 0; t < 2; ++t) {
                    const int nt = 2 * ks + t;
                    const float u0c = xA + cpre[ks][t];
                    const float u1c = xA + cpre1[ks][t];
                    const float v0c = xB + cpre[ks][t];
                    const float v1c = xB + cpre1[ks][t];
                    float p0 = fsqrt_ap(fmaxf(fmaf(-2.f, S[mt][nt][0], u0c), 1.f));
                    float p1 = fsqrt_ap(fmaxf(fmaf(-2.f, S[mt][nt][1], u1c), 1.f));
                    float p2 = fsqrt_ap(fmaxf(fmaf(-2.f, S[mt][nt][2], v0c), 1.f));
                    float p3 = fsqrt_ap(fmaxf(fmaf(-2.f, S[mt][nt][3], v1c), 1.f));
                    __half2 hA = __floats2half2_rn(p0, p1);
                    __half2 hB = __floats2half2_rn(p2, p3);
                    afrag[mt][2 * t]     = *(uint32_t*)&hA;
                    afrag[mt][2 * t + 1] = *(uint32_t*)&hB;
                }
            }
            #pragma unroll
            for (int nt = 0; nt < 8; ++nt) {
                mma_f16(O[0][nt], afrag[0], &wb[cur][nt >> 1][(nt & 1) * 2]);
                mma_f16(O[1][nt], afrag[1], &wb[cur][nt >> 1][(nt & 1) * 2]);
            }
        }

        // ---- flush O at tile boundary / end ----
        if (u + 1 == u1 || ((u + 1) >> 6) != tile) {
            #pragma unroll
            for (int mt = 0; mt < 2; ++mt) {
                int rA = tile * BD + RM + mt * 16 + gid;
                #pragma unroll
                for (int nt = 0; nt < 8; ++nt) {
                    int c0 = nt * 8 + 2 * ctg;
                    atomicAdd(&out[(size_t)rA * LD + c0],           O[mt][nt][0]);
                    atomicAdd(&out[(size_t)rA * LD + c0 + 1],       O[mt][nt][1]);
                    atomicAdd(&out[(size_t)(rA + 8) * LD + c0],     O[mt][nt][2]);
                    atomicAdd(&out[(size_t)(rA + 8) * LD + c0 + 1], O[mt][nt][3]);
                    O[mt][nt][0] = O[mt][nt][1] = O[mt][nt][2] = O[mt][nt][3] = 0.f;
                }
            }
        }
    }
}

// ---------------------------------------------------------------------------
extern "C" void kernel_launch(void* const* d_in, const int* in_sizes, int n_in,
                              void* d_out, int out_size) {
    const float* xs     = (const float*)d_in[0];
    const float* centre = (const float*)d_in[1];
    const float* weight = (const float*)d_in[2];
    float* out = (float*)d_out;

    int nsm = 0;
    cudaDeviceGetAttribute(&nsm, cudaDevAttrMultiProcessorCount, 0);
    if (nsm <= 0) nsm = 128;
    if (nsm > UNITS) nsm = UNITS;

    cudaFuncSetAttribute(rbfn_main_kernel,
                         cudaFuncAttributeMaxDynamicSharedMemorySize, SMEM_BYTES);

    prologue_kernel<<<128 + 512, THREADS>>>(xs, centre, weight, out);

    // Launch main kernel with programmatic dependent launch (PDL).
    cudaLaunchConfig_t cfg = {};
    cfg.gridDim = dim3((unsigned)nsm, 1, 1);
    cfg.blockDim = dim3(THREADS, 1, 1);
    cfg.dynamicSmemBytes = SMEM_BYTES;
    cudaLaunchAttribute attrs[1];
    attrs[0].id = cudaLaunchAttributeProgrammaticStreamSerialization;
    attrs[0].val.programmaticStreamSerializationAllowed = 1;
    cfg.attrs = attrs;
    cfg.numAttrs = 1;
    cudaError_t err = cudaLaunchKernelEx(&cfg, rbfn_main_kernel, out);
    if (err != cudaSuccess) {
        // Fallback: plain launch (griddepcontrol.wait is a no-op without PDL).
        rbfn_main_kernel<<<nsm, THREADS, SMEM_BYTES>>>(out);
    }
}